// round 7
// baseline (speedup 1.0000x reference)
#include <cuda_runtime.h>
#include <cuda_fp16.h>
#include <cstdint>

#define BATCH 16
#define CIN   256
#define DMODEL 256
#define HEADS 8
#define NPH   32
#define HDIM  56
#define LTOT  3136
#define KWIN  9

// ---------------- device scratch ----------------
__device__ float g_wq[BATCH * HEADS * CIN];
__device__ float g_s[BATCH * HEADS * LTOT];
__device__ float g_v[BATCH * DMODEL * LTOT];
__device__ __align__(16) __half g_xhi[BATCH * CIN * LTOT];
__device__ __align__(16) __half g_xlo[BATCH * CIN * LTOT];
__device__ __align__(16) __half g_ohi[BATCH * DMODEL * LTOT];
__device__ __align__(16) __half g_olo[BATCH * DMODEL * LTOT];
__device__ __align__(16) __half g_wvhi[DMODEL * CIN];
__device__ __align__(16) __half g_wvlo[DMODEL * CIN];
__device__ __align__(16) __half g_wphi[DMODEL * DMODEL];
__device__ __align__(16) __half g_wplo[DMODEL * DMODEL];

// ---------------- PTX helpers ----------------
__device__ __forceinline__ uint32_t smem_u32(const void* p) {
    uint32_t a;
    asm("{ .reg .u64 t; cvta.to.shared.u64 t, %1; cvt.u32.u64 %0, t; }" : "=r"(a) : "l"(p));
    return a;
}
__device__ __forceinline__ void ldmA4(uint32_t* r, uint32_t addr) {
    asm volatile("ldmatrix.sync.aligned.m8n8.x4.shared.b16 {%0,%1,%2,%3}, [%4];"
                 : "=r"(r[0]), "=r"(r[1]), "=r"(r[2]), "=r"(r[3]) : "r"(addr));
}
__device__ __forceinline__ void ldmBt4(uint32_t* r, uint32_t addr) {
    asm volatile("ldmatrix.sync.aligned.m8n8.x4.trans.shared.b16 {%0,%1,%2,%3}, [%4];"
                 : "=r"(r[0]), "=r"(r[1]), "=r"(r[2]), "=r"(r[3]) : "r"(addr));
}
__device__ __forceinline__ void hmma(float* d, const uint32_t* a, const uint32_t* b) {
    asm volatile("mma.sync.aligned.m16n8k16.row.col.f32.f16.f16.f32 "
                 "{%0,%1,%2,%3}, {%4,%5,%6,%7}, {%8,%9}, {%0,%1,%2,%3};"
                 : "+f"(d[0]), "+f"(d[1]), "+f"(d[2]), "+f"(d[3])
                 : "r"(a[0]), "r"(a[1]), "r"(a[2]), "r"(a[3]), "r"(b[0]), "r"(b[1]));
}
__device__ __forceinline__ void cp16(uint32_t dst, const void* src) {
    asm volatile("cp.async.cg.shared.global [%0], [%1], 16;" :: "r"(dst), "l"(src));
}
#define CP_COMMIT() asm volatile("cp.async.commit_group;" ::: "memory")
__device__ __forceinline__ uint32_t sw128(uint32_t b) { return b ^ ((b >> 3) & 0x70); }

// ---------------- K0: hi/lo fp16 split (weights) ----------------
__global__ void split_kernel(const float* __restrict__ src, __half* __restrict__ hi,
                             __half* __restrict__ lo, int n4) {
    int i = blockIdx.x * 256 + threadIdx.x;
    if (i >= n4) return;
    float4 v = reinterpret_cast<const float4*>(src)[i];
    float vv[4] = {v.x, v.y, v.z, v.w};
    __half h[4], l[4];
#pragma unroll
    for (int j = 0; j < 4; j++) {
        h[j] = __float2half(vv[j]);
        l[j] = __float2half(vv[j] - __half2float(h[j]));
    }
    __half2* H = reinterpret_cast<__half2*>(hi);
    __half2* L = reinterpret_cast<__half2*>(lo);
    H[2 * i]     = __half2(h[0], h[1]);
    H[2 * i + 1] = __half2(h[2], h[3]);
    L[2 * i]     = __half2(l[0], l[1]);
    L[2 * i + 1] = __half2(l[2], l[3]);
}

// ---------------- K1: wq[b,h,c] = sum_n q[b,h*32+n] * Wk[h*32+n, c] ----------------
__global__ void wq_kernel(const float* __restrict__ q, const float* __restrict__ Wk) {
    int bh = blockIdx.x;
    int b = bh >> 3, h = bh & 7;
    __shared__ float qs[NPH];
    if (threadIdx.x < NPH) qs[threadIdx.x] = q[b * DMODEL + h * NPH + threadIdx.x];
    __syncthreads();
    int c = threadIdx.x;
    float acc = 0.f;
#pragma unroll
    for (int n = 0; n < NPH; n++) acc += qs[n] * Wk[(h * NPH + n) * CIN + c];
    g_wq[bh * CIN + c] = acc;
}

// ---------------- K2: s + x hi/lo split fused (float4 ILP) ----------------
// grid (49, 16), block 256 = 16 l-quads x 16 c-splits
__global__ void __launch_bounds__(256) s_split_kernel(const float* __restrict__ x) {
    __shared__ float wq_s[HEADS * CIN];         // 8 KB
    __shared__ float red[16][HEADS][64];        // 32 KB
    const int b = blockIdx.y;
    for (int i = threadIdx.x; i < HEADS * CIN; i += 256)
        wq_s[i] = g_wq[b * HEADS * CIN + i];
    __syncthreads();

    const int lq = threadIdx.x & 15;            // l-quad index
    const int cs = threadIdx.x >> 4;            // 0..15
    const int l = blockIdx.x * 64 + lq * 4;
    const float* xb = x + (size_t)b * CIN * LTOT;
    __half* xhi = g_xhi + (size_t)b * CIN * LTOT;
    __half* xlo = g_xlo + (size_t)b * CIN * LTOT;

    float acc[HEADS][4] = {};
#pragma unroll 4
    for (int cc = 0; cc < 16; cc++) {
        int c = cs * 16 + cc;
        size_t idx = (size_t)c * LTOT + l;
        float4 v = *reinterpret_cast<const float4*>(xb + idx);
        __half2 h01 = __float22half2_rn(make_float2(v.x, v.y));
        __half2 h23 = __float22half2_rn(make_float2(v.z, v.w));
        float2 r01 = __half22float2(h01), r23 = __half22float2(h23);
        __half2 l01 = __float22half2_rn(make_float2(v.x - r01.x, v.y - r01.y));
        __half2 l23 = __float22half2_rn(make_float2(v.z - r23.x, v.w - r23.y));
        uint2 hp, lp2;
        hp.x = *reinterpret_cast<uint32_t*>(&h01); hp.y = *reinterpret_cast<uint32_t*>(&h23);
        lp2.x = *reinterpret_cast<uint32_t*>(&l01); lp2.y = *reinterpret_cast<uint32_t*>(&l23);
        *reinterpret_cast<uint2*>(xhi + idx) = hp;
        *reinterpret_cast<uint2*>(xlo + idx) = lp2;
#pragma unroll
        for (int hh = 0; hh < HEADS; hh++) {
            float w = wq_s[hh * CIN + c];
            acc[hh][0] += w * v.x;
            acc[hh][1] += w * v.y;
            acc[hh][2] += w * v.z;
            acc[hh][3] += w * v.w;
        }
    }
#pragma unroll
    for (int hh = 0; hh < HEADS; hh++)
#pragma unroll
        for (int j = 0; j < 4; j++) red[cs][hh][lq * 4 + j] = acc[hh][j];
    __syncthreads();
    for (int i = threadIdx.x; i < HEADS * 64; i += 256) {
        int hh = i >> 6, l2i = i & 63;
        float s = 0.f;
#pragma unroll
        for (int c16 = 0; c16 < 16; c16++) s += red[c16][hh][l2i];
        g_s[(size_t)(b * HEADS + hh) * LTOT + blockIdx.x * 64 + l2i] = s;
    }
}

// ---------------- K3: HMMA compensated GEMM, M=256 x N=64 per CTA ----------------
// stage (80KB): Ahi 32K | Alo 32K | Xhi 8K | Xlo 8K; two stages = 160 KB.
#define STAGE_BYTES 81920
__global__ void __launch_bounds__(256, 1) hgemm(
    const __half* __restrict__ Ahi, const __half* __restrict__ Alo,
    const __half* __restrict__ Xhi, const __half* __restrict__ Xlo,
    float* __restrict__ C) {
    extern __shared__ __align__(1024) unsigned char sb[];
    const uint32_t s0 = smem_u32(sb);

    const int tid = threadIdx.x;
    const int wid = tid >> 5, lane = tid & 31;
    const int l0 = blockIdx.x * 64;
    const int b  = blockIdx.y;

    const int m_base = (wid & 3) * 64;     // warp tile 64 M x 32 N
    const int n_base = (wid >> 2) * 32;

    const __half* Xhi_b = Xhi + (size_t)b * CIN * LTOT;
    const __half* Xlo_b = Xlo + (size_t)b * CIN * LTOT;

    float acc[4][4][4];
#pragma unroll
    for (int mt = 0; mt < 4; mt++)
#pragma unroll
        for (int nt = 0; nt < 4; nt++)
#pragma unroll
            for (int i = 0; i < 4; i++) acc[mt][nt][i] = 0.f;

    auto load_chunk = [&](int c) {
        const int st = c & 1;
        const int k0 = c * 64;
        uint32_t dAhi = s0 + st * STAGE_BYTES;
        uint32_t dAlo = dAhi + 32768;
        uint32_t dXhi = dAhi + 65536;
        uint32_t dXlo = dAhi + 73728;
#pragma unroll
        for (int j = 0; j < 8; j++) {      // A: 256 rows x 64 k halves
            int idx = tid + j * 256;
            int row = idx >> 3, ch = idx & 7;
            uint32_t off = sw128(row * 128 + ch * 16);
            size_t gidx = (size_t)row * CIN + k0 + ch * 8;
            cp16(dAhi + off, Ahi + gidx);
            cp16(dAlo + off, Alo + gidx);
        }
#pragma unroll
        for (int j = 0; j < 2; j++) {      // X: 64 rows x 64 n halves
            int idx = tid + j * 256;
            int row = idx >> 3, ch = idx & 7;
            uint32_t off = sw128(row * 128 + ch * 16);
            size_t gidx = (size_t)(k0 + row) * LTOT + l0 + ch * 8;
            cp16(dXhi + off, Xhi_b + gidx);
            cp16(dXlo + off, Xlo_b + gidx);
        }
        CP_COMMIT();
    };

    load_chunk(0);
    const int b3 = lane >> 3, r8 = lane & 7;

    for (int c = 0; c < 4; c++) {
        if (c + 1 < 4) {
            load_chunk(c + 1);
            asm volatile("cp.async.wait_group 1;" ::: "memory");
        } else {
            asm volatile("cp.async.wait_group 0;" ::: "memory");
        }
        __syncthreads();

        const int st = c & 1;
        const uint32_t sAhi = s0 + st * STAGE_BYTES;
        const uint32_t sAlo = sAhi + 32768;
        const uint32_t sXhi = sAhi + 65536;
        const uint32_t sXlo = sAhi + 73728;

#pragma unroll
        for (int kk = 0; kk < 4; kk++) {
            uint32_t bhi[2][4], blo[2][4];
#pragma unroll
            for (int g = 0; g < 2; g++) {
                int krow = kk * 16 + (lane & 15);
                int ncol = n_base + g * 16 + ((lane >> 4) << 3);
                uint32_t byte = sw128((uint32_t)(krow * 128 + ncol * 2));
                ldmBt4(bhi[g], sXhi + byte);
                ldmBt4(blo[g], sXlo + byte);
            }
#pragma unroll
            for (int mt = 0; mt < 4; mt++) {
                uint32_t ahi[4], alo[4];
                int row = m_base + mt * 16 + ((b3 & 1) << 3) + r8;
                uint32_t byte = sw128((uint32_t)(row * 128 + kk * 32 + ((b3 >> 1) << 4)));
                ldmA4(ahi, sAhi + byte);
                ldmA4(alo, sAlo + byte);
#pragma unroll
                for (int g = 0; g < 2; g++)
#pragma unroll
                    for (int h = 0; h < 2; h++) {
                        float* a = acc[mt][g * 2 + h];
                        hmma(a, ahi, &bhi[g][h * 2]);   // hh
                        hmma(a, ahi, &blo[g][h * 2]);   // hl
                        hmma(a, alo, &bhi[g][h * 2]);   // lh
                    }
            }
        }
        __syncthreads();
    }

    const int g = lane >> 2, j2 = (lane & 3) * 2;
    float* Cb = C + (size_t)b * DMODEL * LTOT;
#pragma unroll
    for (int mt = 0; mt < 4; mt++) {
        int mrow = m_base + mt * 16 + g;
#pragma unroll
        for (int nt = 0; nt < 4; nt++) {
            int col = l0 + n_base + nt * 8 + j2;
            *reinterpret_cast<float2*>(Cb + (size_t)mrow * LTOT + col) =
                make_float2(acc[mt][nt][0], acc[mt][nt][1]);
            *reinterpret_cast<float2*>(Cb + (size_t)(mrow + 8) * LTOT + col) =
                make_float2(acc[mt][nt][2], acc[mt][nt][3]);
        }
    }
}

// ---------------- K4: fused softmax + AV gather, fp16 hi/lo output ----------------
__global__ void __launch_bounds__(256) attn_av_kernel(
    const float* __restrict__ pos_emb, const float* __restrict__ Wlin) {
    __shared__ float sm_at[KWIN][64];
    const int bh = blockIdx.y;
    const int b = bh >> 3, h = bh & 7;
    const int l0 = blockIdx.x * 64;
    const int tid = threadIdx.x;

    if (tid < 64) {
        float scale = Wlin[0] + Wlin[1] + Wlin[2] + Wlin[3];
        int l = l0 + tid;
        int y = l / HDIM, xx = l % HDIM;
        const float* sp = g_s + (size_t)bh * LTOT;
        float logit[KWIN];
#pragma unroll
        for (int kh = 0; kh < 3; kh++)
#pragma unroll
            for (int kw = 0; kw < 3; kw++) {
                int yy = y + kh - 1, xz = xx + kw - 1;
                float sv = (yy >= 0 && yy < HDIM && xz >= 0 && xz < HDIM)
                               ? sp[yy * HDIM + xz] : 0.f;
                logit[kh * 3 + kw] = sv + pos_emb[kh + kw];
            }
        float m = logit[0];
#pragma unroll
        for (int k = 1; k < KWIN; k++) m = fmaxf(m, logit[k]);
        float e[KWIN], sum = 0.f;
#pragma unroll
        for (int k = 0; k < KWIN; k++) { e[k] = __expf(logit[k] - m); sum += e[k]; }
        float inv = scale / sum;
#pragma unroll
        for (int k = 0; k < KWIN; k++) sm_at[k][tid] = e[k] * inv;
    }
    __syncthreads();

    const int lp = tid & 31;
    const int dg = tid >> 5;
    float att[2][KWIN];
    int off[2][KWIN];
#pragma unroll
    for (int e = 0; e < 2; e++) {
        int ll = lp * 2 + e;
        int l = l0 + ll;
        int y = l / HDIM, xx = l % HDIM;
#pragma unroll
        for (int kh = 0; kh < 3; kh++)
#pragma unroll
            for (int kw = 0; kw < 3; kw++) {
                int k = kh * 3 + kw;
                int yy = y + kh - 1, xz = xx + kw - 1;
                bool ok = (yy >= 0 && yy < HDIM && xz >= 0 && xz < HDIM);
                att[e][k] = ok ? sm_at[k][ll] : 0.f;
                off[e][k] = ok ? yy * HDIM + xz : 0;
            }
    }
    const size_t base = (size_t)(b * DMODEL + h * NPH + dg * 4) * LTOT;
#pragma unroll
    for (int dd = 0; dd < 4; dd++) {
        const float* vp = g_v + base + (size_t)dd * LTOT;
        float o[2];
#pragma unroll
        for (int e = 0; e < 2; e++) {
            float a = 0.f;
#pragma unroll
            for (int k = 0; k < KWIN; k++) a += att[e][k] * vp[off[e][k]];
            o[e] = a;
        }
        __half2 h2 = __float22half2_rn(make_float2(o[0], o[1]));
        float2 hr = __half22float2(h2);
        __half2 l2 = __float22half2_rn(make_float2(o[0] - hr.x, o[1] - hr.y));
        size_t oidx = base + (size_t)dd * LTOT + l0 + lp * 2;
        *reinterpret_cast<__half2*>(g_ohi + oidx) = h2;
        *reinterpret_cast<__half2*>(g_olo + oidx) = l2;
    }
}

// ---------------- host launcher ----------------
extern "C" void kernel_launch(void* const* d_in, const int* in_sizes, int n_in,
                              void* d_out, int out_size) {
    const float* x       = (const float*)d_in[0];
    const float* q       = (const float*)d_in[1];
    const float* Wk      = (const float*)d_in[2];
    const float* Wv      = (const float*)d_in[3];
    const float* pos_emb = (const float*)d_in[4];
    const float* Wlin    = (const float*)d_in[5];
    const float* Wproj   = (const float*)d_in[6];
    float* out = (float*)d_out;

    void *pv, *pxhi, *pxlo, *pohi, *polo, *pwvhi, *pwvlo, *pwphi, *pwplo;
    cudaGetSymbolAddress(&pv, g_v);
    cudaGetSymbolAddress(&pxhi, g_xhi);
    cudaGetSymbolAddress(&pxlo, g_xlo);
    cudaGetSymbolAddress(&pohi, g_ohi);
    cudaGetSymbolAddress(&polo, g_olo);
    cudaGetSymbolAddress(&pwvhi, g_wvhi);
    cudaGetSymbolAddress(&pwvlo, g_wvlo);
    cudaGetSymbolAddress(&pwphi, g_wphi);
    cudaGetSymbolAddress(&pwplo, g_wplo);

    static bool attr_set = false;
    if (!attr_set) {
        cudaFuncSetAttribute(hgemm, cudaFuncAttributeMaxDynamicSharedMemorySize,
                             2 * STAGE_BYTES);
        attr_set = true;
    }

    const int WN4 = DMODEL * CIN / 4;
    const int SMEM = 2 * STAGE_BYTES;

    wq_kernel<<<BATCH * HEADS, 256>>>(q, Wk);
    split_kernel<<<(WN4 + 255) / 256, 256>>>(Wv, (__half*)pwvhi, (__half*)pwvlo, WN4);
    split_kernel<<<(WN4 + 255) / 256, 256>>>(Wproj, (__half*)pwphi, (__half*)pwplo, WN4);
    s_split_kernel<<<dim3(LTOT / 64, BATCH), 256>>>(x);

    hgemm<<<dim3(LTOT / 64, BATCH), 256, SMEM>>>(
        (const __half*)pwvhi, (const __half*)pwvlo,
        (const __half*)pxhi, (const __half*)pxlo, (float*)pv);

    attn_av_kernel<<<dim3(LTOT / 64, BATCH * HEADS), 256>>>(pos_emb, Wlin);

    hgemm<<<dim3(LTOT / 64, BATCH), 256, SMEM>>>(
        (const __half*)pwphi, (const __half*)pwplo,
        (const __half*)pohi, (const __half*)polo, out);
}

// round 8
// speedup vs baseline: 1.0894x; 1.0894x over previous
#include <cuda_runtime.h>
#include <cuda_fp16.h>
#include <cstdint>

#define BATCH 16
#define CIN   256
#define DMODEL 256
#define HEADS 8
#define NPH   32
#define HDIM  56
#define LTOT  3136
#define KWIN  9

// ---------------- device scratch ----------------
__device__ float g_wq[BATCH * HEADS * CIN];
__device__ float g_s[BATCH * HEADS * LTOT];
__device__ float g_v[BATCH * DMODEL * LTOT];
__device__ __align__(16) __half g_xhi[BATCH * CIN * LTOT];
__device__ __align__(16) __half g_xlo[BATCH * CIN * LTOT];
__device__ __align__(16) __half g_ohi[BATCH * DMODEL * LTOT];
__device__ __align__(16) __half g_olo[BATCH * DMODEL * LTOT];
__device__ __align__(16) __half g_wvhi[DMODEL * CIN];
__device__ __align__(16) __half g_wvlo[DMODEL * CIN];
__device__ __align__(16) __half g_wphi[DMODEL * DMODEL];
__device__ __align__(16) __half g_wplo[DMODEL * DMODEL];

// ---------------- PTX helpers ----------------
__device__ __forceinline__ uint32_t smem_u32(const void* p) {
    uint32_t a;
    asm("{ .reg .u64 t; cvta.to.shared.u64 t, %1; cvt.u32.u64 %0, t; }" : "=r"(a) : "l"(p));
    return a;
}
__device__ __forceinline__ void ldmA4(uint32_t* r, uint32_t addr) {
    asm volatile("ldmatrix.sync.aligned.m8n8.x4.shared.b16 {%0,%1,%2,%3}, [%4];"
                 : "=r"(r[0]), "=r"(r[1]), "=r"(r[2]), "=r"(r[3]) : "r"(addr));
}
__device__ __forceinline__ void ldmBt4(uint32_t* r, uint32_t addr) {
    asm volatile("ldmatrix.sync.aligned.m8n8.x4.trans.shared.b16 {%0,%1,%2,%3}, [%4];"
                 : "=r"(r[0]), "=r"(r[1]), "=r"(r[2]), "=r"(r[3]) : "r"(addr));
}
__device__ __forceinline__ void hmma(float* d, const uint32_t* a, const uint32_t* b) {
    asm volatile("mma.sync.aligned.m16n8k16.row.col.f32.f16.f16.f32 "
                 "{%0,%1,%2,%3}, {%4,%5,%6,%7}, {%8,%9}, {%0,%1,%2,%3};"
                 : "+f"(d[0]), "+f"(d[1]), "+f"(d[2]), "+f"(d[3])
                 : "r"(a[0]), "r"(a[1]), "r"(a[2]), "r"(a[3]), "r"(b[0]), "r"(b[1]));
}
__device__ __forceinline__ void cp16(uint32_t dst, const void* src) {
    asm volatile("cp.async.cg.shared.global [%0], [%1], 16;" :: "r"(dst), "l"(src));
}
#define CP_COMMIT() asm volatile("cp.async.commit_group;" ::: "memory")
__device__ __forceinline__ uint32_t sw128(uint32_t b) { return b ^ ((b >> 3) & 0x70); }

// ---------------- K0: hi/lo fp16 split (weights) ----------------
__global__ void split_kernel(const float* __restrict__ src, __half* __restrict__ hi,
                             __half* __restrict__ lo, int n4) {
    int i = blockIdx.x * 256 + threadIdx.x;
    if (i >= n4) return;
    float4 v = reinterpret_cast<const float4*>(src)[i];
    float vv[4] = {v.x, v.y, v.z, v.w};
    __half h[4], l[4];
#pragma unroll
    for (int j = 0; j < 4; j++) {
        h[j] = __float2half(vv[j]);
        l[j] = __float2half(vv[j] - __half2float(h[j]));
    }
    __half2* H = reinterpret_cast<__half2*>(hi);
    __half2* L = reinterpret_cast<__half2*>(lo);
    H[2 * i]     = __half2(h[0], h[1]);
    H[2 * i + 1] = __half2(h[2], h[3]);
    L[2 * i]     = __half2(l[0], l[1]);
    L[2 * i + 1] = __half2(l[2], l[3]);
}

// ---------------- K1: wq[b,h,c] = sum_n q[b,h*32+n] * Wk[h*32+n, c] ----------------
__global__ void wq_kernel(const float* __restrict__ q, const float* __restrict__ Wk) {
    int bh = blockIdx.x;
    int b = bh >> 3, h = bh & 7;
    __shared__ float qs[NPH];
    if (threadIdx.x < NPH) qs[threadIdx.x] = q[b * DMODEL + h * NPH + threadIdx.x];
    __syncthreads();
    int c = threadIdx.x;
    float acc = 0.f;
#pragma unroll
    for (int n = 0; n < NPH; n++) acc += qs[n] * Wk[(h * NPH + n) * CIN + c];
    g_wq[bh * CIN + c] = acc;
}

// ---------------- K2: s + x hi/lo split fused (vectorized, R6 + deeper unroll) ----------------
// grid (49, 16), block 256 = 32 l-pairs x 8 c-splits
__global__ void __launch_bounds__(256) s_split_kernel(const float* __restrict__ x) {
    __shared__ float wq_s[HEADS * CIN];         // 8 KB
    __shared__ float red[8][HEADS][64];         // 16 KB
    const int b = blockIdx.y;
    {
        const float4* src = reinterpret_cast<const float4*>(g_wq + b * HEADS * CIN);
        float4* dst = reinterpret_cast<float4*>(wq_s);
        for (int i = threadIdx.x; i < HEADS * CIN / 4; i += 256) dst[i] = src[i];
    }
    __syncthreads();

    const int lp = threadIdx.x & 31;            // l-pair index
    const int cs = threadIdx.x >> 5;            // 0..7
    const int l = blockIdx.x * 64 + lp * 2;
    const float* xb = x + (size_t)b * CIN * LTOT;
    __half* xhi = g_xhi + (size_t)b * CIN * LTOT;
    __half* xlo = g_xlo + (size_t)b * CIN * LTOT;

    float acc[HEADS][2] = {};
#pragma unroll 8
    for (int cc = 0; cc < 32; cc++) {
        int c = cs * 32 + cc;
        size_t idx = (size_t)c * LTOT + l;
        float2 v = *reinterpret_cast<const float2*>(xb + idx);
        __half2 h2 = __float22half2_rn(v);
        float2 hr = __half22float2(h2);
        __half2 l2 = __float22half2_rn(make_float2(v.x - hr.x, v.y - hr.y));
        *reinterpret_cast<__half2*>(xhi + idx) = h2;
        *reinterpret_cast<__half2*>(xlo + idx) = l2;
#pragma unroll
        for (int hh = 0; hh < HEADS; hh++) {
            float w = wq_s[hh * CIN + c];
            acc[hh][0] += w * v.x;
            acc[hh][1] += w * v.y;
        }
    }
#pragma unroll
    for (int hh = 0; hh < HEADS; hh++) {
        red[cs][hh][lp * 2]     = acc[hh][0];
        red[cs][hh][lp * 2 + 1] = acc[hh][1];
    }
    __syncthreads();
    for (int i = threadIdx.x; i < HEADS * 64; i += 256) {
        int hh = i >> 6, l2i = i & 63;
        float s = 0.f;
#pragma unroll
        for (int c8 = 0; c8 < 8; c8++) s += red[c8][hh][l2i];
        g_s[(size_t)(b * HEADS + hh) * LTOT + blockIdx.x * 64 + l2i] = s;
    }
}

// ---------------- K3: HMMA compensated GEMM, all-fp16 cp.async feed (R6 config) ----------------
#define STAGE_BYTES 49152
__global__ void __launch_bounds__(256, 2) hgemm(
    const __half* __restrict__ Ahi, const __half* __restrict__ Alo,
    const __half* __restrict__ Xhi, const __half* __restrict__ Xlo,
    float* __restrict__ C) {
    extern __shared__ __align__(1024) unsigned char sb[];
    const uint32_t s0 = smem_u32(sb);

    const int tid = threadIdx.x;
    const int wid = tid >> 5, lane = tid & 31;
    const int l0 = blockIdx.x * 64;
    const int m0 = blockIdx.y * 128;
    const int b  = blockIdx.z;

    const int m_base = (wid >> 1) * 32;
    const int n_base = (wid & 1) * 32;

    const __half* Xhi_b = Xhi + (size_t)b * CIN * LTOT;
    const __half* Xlo_b = Xlo + (size_t)b * CIN * LTOT;

    float acc[2][4][4];
#pragma unroll
    for (int mt = 0; mt < 2; mt++)
#pragma unroll
        for (int nt = 0; nt < 4; nt++)
#pragma unroll
            for (int i = 0; i < 4; i++) acc[mt][nt][i] = 0.f;

    auto load_chunk = [&](int c) {
        const int st = c & 1;
        const int k0 = c * 64;
        uint32_t dAhi = s0 + st * STAGE_BYTES;
        uint32_t dAlo = dAhi + 16384;
        uint32_t dXhi = dAhi + 32768;
        uint32_t dXlo = dAhi + 40960;
#pragma unroll
        for (int j = 0; j < 4; j++) {
            int idx = tid + j * 256;
            int row = idx >> 3, ch = idx & 7;
            uint32_t off = sw128(row * 128 + ch * 16);
            size_t gidx = (size_t)(m0 + row) * CIN + k0 + ch * 8;
            cp16(dAhi + off, Ahi + gidx);
            cp16(dAlo + off, Alo + gidx);
        }
#pragma unroll
        for (int j = 0; j < 2; j++) {
            int idx = tid + j * 256;
            int row = idx >> 3, ch = idx & 7;
            uint32_t off = sw128(row * 128 + ch * 16);
            size_t gidx = (size_t)(k0 + row) * LTOT + l0 + ch * 8;
            cp16(dXhi + off, Xhi_b + gidx);
            cp16(dXlo + off, Xlo_b + gidx);
        }
        CP_COMMIT();
    };

    load_chunk(0);
    const int b3 = lane >> 3, r8 = lane & 7;

    for (int c = 0; c < 4; c++) {
        if (c + 1 < 4) {
            load_chunk(c + 1);
            asm volatile("cp.async.wait_group 1;" ::: "memory");
        } else {
            asm volatile("cp.async.wait_group 0;" ::: "memory");
        }
        __syncthreads();

        const int st = c & 1;
        const uint32_t sAhi = s0 + st * STAGE_BYTES;
        const uint32_t sAlo = sAhi + 16384;
        const uint32_t sXhi = sAhi + 32768;
        const uint32_t sXlo = sAhi + 40960;

#pragma unroll
        for (int kk = 0; kk < 4; kk++) {
            uint32_t ahi[2][4], alo[2][4], bhi[2][4], blo[2][4];
#pragma unroll
            for (int mt = 0; mt < 2; mt++) {
                int row = m_base + mt * 16 + ((b3 & 1) << 3) + r8;
                uint32_t byte = sw128((uint32_t)(row * 128 + kk * 32 + ((b3 >> 1) << 4)));
                ldmA4(ahi[mt], sAhi + byte);
                ldmA4(alo[mt], sAlo + byte);
            }
#pragma unroll
            for (int g = 0; g < 2; g++) {
                int krow = kk * 16 + (lane & 15);
                int ncol = n_base + g * 16 + ((lane >> 4) << 3);
                uint32_t byte = sw128((uint32_t)(krow * 128 + ncol * 2));
                ldmBt4(bhi[g], sXhi + byte);
                ldmBt4(blo[g], sXlo + byte);
            }
#pragma unroll
            for (int mt = 0; mt < 2; mt++)
#pragma unroll
                for (int g = 0; g < 2; g++)
#pragma unroll
                    for (int h = 0; h < 2; h++) {
                        float* a = acc[mt][g * 2 + h];
                        hmma(a, ahi[mt], &bhi[g][h * 2]);   // hh
                        hmma(a, ahi[mt], &blo[g][h * 2]);   // hl
                        hmma(a, alo[mt], &bhi[g][h * 2]);   // lh
                    }
        }
        __syncthreads();
    }

    const int g = lane >> 2, j2 = (lane & 3) * 2;
    float* Cb = C + (size_t)b * DMODEL * LTOT;
#pragma unroll
    for (int mt = 0; mt < 2; mt++) {
        int mrow = m0 + m_base + mt * 16 + g;
#pragma unroll
        for (int nt = 0; nt < 4; nt++) {
            int col = l0 + n_base + nt * 8 + j2;
            *reinterpret_cast<float2*>(Cb + (size_t)mrow * LTOT + col) =
                make_float2(acc[mt][nt][0], acc[mt][nt][1]);
            *reinterpret_cast<float2*>(Cb + (size_t)(mrow + 8) * LTOT + col) =
                make_float2(acc[mt][nt][2], acc[mt][nt][3]);
        }
    }
}

// ---------------- K4: fused softmax + AV gather, fp16 hi/lo output ----------------
__global__ void __launch_bounds__(256) attn_av_kernel(
    const float* __restrict__ pos_emb, const float* __restrict__ Wlin) {
    __shared__ float sm_at[KWIN][64];
    const int bh = blockIdx.y;
    const int b = bh >> 3, h = bh & 7;
    const int l0 = blockIdx.x * 64;
    const int tid = threadIdx.x;

    if (tid < 64) {
        float scale = Wlin[0] + Wlin[1] + Wlin[2] + Wlin[3];
        int l = l0 + tid;
        int y = l / HDIM, xx = l % HDIM;
        const float* sp = g_s + (size_t)bh * LTOT;
        float logit[KWIN];
#pragma unroll
        for (int kh = 0; kh < 3; kh++)
#pragma unroll
            for (int kw = 0; kw < 3; kw++) {
                int yy = y + kh - 1, xz = xx + kw - 1;
                float sv = (yy >= 0 && yy < HDIM && xz >= 0 && xz < HDIM)
                               ? sp[yy * HDIM + xz] : 0.f;
                logit[kh * 3 + kw] = sv + pos_emb[kh + kw];
            }
        float m = logit[0];
#pragma unroll
        for (int k = 1; k < KWIN; k++) m = fmaxf(m, logit[k]);
        float e[KWIN], sum = 0.f;
#pragma unroll
        for (int k = 0; k < KWIN; k++) { e[k] = __expf(logit[k] - m); sum += e[k]; }
        float inv = scale / sum;
#pragma unroll
        for (int k = 0; k < KWIN; k++) sm_at[k][tid] = e[k] * inv;
    }
    __syncthreads();

    const int lp = tid & 31;
    const int dg = tid >> 5;
    float att[2][KWIN];
    int off[2][KWIN];
#pragma unroll
    for (int e = 0; e < 2; e++) {
        int ll = lp * 2 + e;
        int l = l0 + ll;
        int y = l / HDIM, xx = l % HDIM;
#pragma unroll
        for (int kh = 0; kh < 3; kh++)
#pragma unroll
            for (int kw = 0; kw < 3; kw++) {
                int k = kh * 3 + kw;
                int yy = y + kh - 1, xz = xx + kw - 1;
                bool ok = (yy >= 0 && yy < HDIM && xz >= 0 && xz < HDIM);
                att[e][k] = ok ? sm_at[k][ll] : 0.f;
                off[e][k] = ok ? yy * HDIM + xz : 0;
            }
    }
    const size_t base = (size_t)(b * DMODEL + h * NPH + dg * 4) * LTOT;
#pragma unroll
    for (int dd = 0; dd < 4; dd++) {
        const float* vp = g_v + base + (size_t)dd * LTOT;
        float o[2];
#pragma unroll
        for (int e = 0; e < 2; e++) {
            float a = 0.f;
#pragma unroll
            for (int k = 0; k < KWIN; k++) a += att[e][k] * vp[off[e][k]];
            o[e] = a;
        }
        __half2 h2 = __float22half2_rn(make_float2(o[0], o[1]));
        float2 hr = __half22float2(h2);
        __half2 l2 = __float22half2_rn(make_float2(o[0] - hr.x, o[1] - hr.y));
        size_t oidx = base + (size_t)dd * LTOT + l0 + lp * 2;
        *reinterpret_cast<__half2*>(g_ohi + oidx) = h2;
        *reinterpret_cast<__half2*>(g_olo + oidx) = l2;
    }
}

// ---------------- host launcher ----------------
extern "C" void kernel_launch(void* const* d_in, const int* in_sizes, int n_in,
                              void* d_out, int out_size) {
    const float* x       = (const float*)d_in[0];
    const float* q       = (const float*)d_in[1];
    const float* Wk      = (const float*)d_in[2];
    const float* Wv      = (const float*)d_in[3];
    const float* pos_emb = (const float*)d_in[4];
    const float* Wlin    = (const float*)d_in[5];
    const float* Wproj   = (const float*)d_in[6];
    float* out = (float*)d_out;

    void *pv, *pxhi, *pxlo, *pohi, *polo, *pwvhi, *pwvlo, *pwphi, *pwplo;
    cudaGetSymbolAddress(&pv, g_v);
    cudaGetSymbolAddress(&pxhi, g_xhi);
    cudaGetSymbolAddress(&pxlo, g_xlo);
    cudaGetSymbolAddress(&pohi, g_ohi);
    cudaGetSymbolAddress(&polo, g_olo);
    cudaGetSymbolAddress(&pwvhi, g_wvhi);
    cudaGetSymbolAddress(&pwvlo, g_wvlo);
    cudaGetSymbolAddress(&pwphi, g_wphi);
    cudaGetSymbolAddress(&pwplo, g_wplo);

    static bool attr_set = false;
    if (!attr_set) {
        cudaFuncSetAttribute(hgemm, cudaFuncAttributeMaxDynamicSharedMemorySize,
                             2 * STAGE_BYTES);
        attr_set = true;
    }

    const int WN4 = DMODEL * CIN / 4;
    const int SMEM = 2 * STAGE_BYTES;

    wq_kernel<<<BATCH * HEADS, 256>>>(q, Wk);
    split_kernel<<<(WN4 + 255) / 256, 256>>>(Wv, (__half*)pwvhi, (__half*)pwvlo, WN4);
    split_kernel<<<(WN4 + 255) / 256, 256>>>(Wproj, (__half*)pwphi, (__half*)pwplo, WN4);
    s_split_kernel<<<dim3(LTOT / 64, BATCH), 256>>>(x);

    hgemm<<<dim3(LTOT / 64, DMODEL / 128, BATCH), 256, SMEM>>>(
        (const __half*)pwvhi, (const __half*)pwvlo,
        (const __half*)pxhi, (const __half*)pxlo, (float*)pv);

    attn_av_kernel<<<dim3(LTOT / 64, BATCH * HEADS), 256>>>(pos_emb, Wlin);

    hgemm<<<dim3(LTOT / 64, DMODEL / 128, BATCH), 256, SMEM>>>(
        (const __half*)pwphi, (const __half*)pwplo,
        (const __half*)pohi, (const __half*)polo, out);
}

// round 9
// speedup vs baseline: 1.4163x; 1.3001x over previous
#include <cuda_runtime.h>
#include <cuda_fp16.h>
#include <cstdint>

#define BATCH 16
#define CIN   256
#define DMODEL 256
#define HEADS 8
#define NPH   32
#define HDIM  56
#define LTOT  3136
#define KWIN  9

// ---------------- device scratch ----------------
__device__ float g_wq[BATCH * HEADS * CIN];
__device__ float g_s[BATCH * HEADS * LTOT];
__device__ float g_v[BATCH * DMODEL * LTOT];
__device__ __align__(16) __half g_xhi[BATCH * CIN * LTOT];
__device__ __align__(16) __half g_ohi[BATCH * DMODEL * LTOT];
__device__ __align__(16) __half g_wvhi[DMODEL * CIN];
__device__ __align__(16) __half g_wvlo[DMODEL * CIN];
__device__ __align__(16) __half g_wphi[DMODEL * DMODEL];
__device__ __align__(16) __half g_wplo[DMODEL * DMODEL];

// ---------------- PTX helpers ----------------
__device__ __forceinline__ uint32_t smem_u32(const void* p) {
    uint32_t a;
    asm("{ .reg .u64 t; cvta.to.shared.u64 t, %1; cvt.u32.u64 %0, t; }" : "=r"(a) : "l"(p));
    return a;
}
__device__ __forceinline__ void ldmA4(uint32_t* r, uint32_t addr) {
    asm volatile("ldmatrix.sync.aligned.m8n8.x4.shared.b16 {%0,%1,%2,%3}, [%4];"
                 : "=r"(r[0]), "=r"(r[1]), "=r"(r[2]), "=r"(r[3]) : "r"(addr));
}
__device__ __forceinline__ void ldmBt4(uint32_t* r, uint32_t addr) {
    asm volatile("ldmatrix.sync.aligned.m8n8.x4.trans.shared.b16 {%0,%1,%2,%3}, [%4];"
                 : "=r"(r[0]), "=r"(r[1]), "=r"(r[2]), "=r"(r[3]) : "r"(addr));
}
__device__ __forceinline__ void hmma(float* d, const uint32_t* a, const uint32_t* b) {
    asm volatile("mma.sync.aligned.m16n8k16.row.col.f32.f16.f16.f32 "
                 "{%0,%1,%2,%3}, {%4,%5,%6,%7}, {%8,%9}, {%0,%1,%2,%3};"
                 : "+f"(d[0]), "+f"(d[1]), "+f"(d[2]), "+f"(d[3])
                 : "r"(a[0]), "r"(a[1]), "r"(a[2]), "r"(a[3]), "r"(b[0]), "r"(b[1]));
}
__device__ __forceinline__ void cp16(uint32_t dst, const void* src) {
    asm volatile("cp.async.cg.shared.global [%0], [%1], 16;" :: "r"(dst), "l"(src));
}
#define CP_COMMIT() asm volatile("cp.async.commit_group;" ::: "memory")
__device__ __forceinline__ uint32_t sw128(uint32_t b) { return b ^ ((b >> 3) & 0x70); }

// ---------------- K0: hi/lo fp16 split (weights) ----------------
__global__ void split_kernel(const float* __restrict__ src, __half* __restrict__ hi,
                             __half* __restrict__ lo, int n4) {
    int i = blockIdx.x * 256 + threadIdx.x;
    if (i >= n4) return;
    float4 v = reinterpret_cast<const float4*>(src)[i];
    float vv[4] = {v.x, v.y, v.z, v.w};
    __half h[4], l[4];
#pragma unroll
    for (int j = 0; j < 4; j++) {
        h[j] = __float2half(vv[j]);
        l[j] = __float2half(vv[j] - __half2float(h[j]));
    }
    __half2* H = reinterpret_cast<__half2*>(hi);
    __half2* L = reinterpret_cast<__half2*>(lo);
    H[2 * i]     = __half2(h[0], h[1]);
    H[2 * i + 1] = __half2(h[2], h[3]);
    L[2 * i]     = __half2(l[0], l[1]);
    L[2 * i + 1] = __half2(l[2], l[3]);
}

// ---------------- K1: wq[b,h,c] = sum_n q[b,h*32+n] * Wk[h*32+n, c] ----------------
__global__ void wq_kernel(const float* __restrict__ q, const float* __restrict__ Wk) {
    int bh = blockIdx.x;
    int b = bh >> 3, h = bh & 7;
    __shared__ float qs[NPH];
    if (threadIdx.x < NPH) qs[threadIdx.x] = q[b * DMODEL + h * NPH + threadIdx.x];
    __syncthreads();
    int c = threadIdx.x;
    float acc = 0.f;
#pragma unroll
    for (int n = 0; n < NPH; n++) acc += qs[n] * Wk[(h * NPH + n) * CIN + c];
    g_wq[bh * CIN + c] = acc;
}

// ---------------- K2: s + x fp16 cast fused ----------------
// grid (49, 16), block 256 = 32 l-pairs x 8 c-splits
__global__ void __launch_bounds__(256) s_split_kernel(const float* __restrict__ x) {
    __shared__ float wq_s[HEADS * CIN];         // 8 KB
    __shared__ float red[8][HEADS][64];         // 16 KB
    const int b = blockIdx.y;
    {
        const float4* src = reinterpret_cast<const float4*>(g_wq + b * HEADS * CIN);
        float4* dst = reinterpret_cast<float4*>(wq_s);
        for (int i = threadIdx.x; i < HEADS * CIN / 4; i += 256) dst[i] = src[i];
    }
    __syncthreads();

    const int lp = threadIdx.x & 31;
    const int cs = threadIdx.x >> 5;
    const int l = blockIdx.x * 64 + lp * 2;
    const float* xb = x + (size_t)b * CIN * LTOT;
    __half* xhi = g_xhi + (size_t)b * CIN * LTOT;

    float acc[HEADS][2] = {};
#pragma unroll 8
    for (int cc = 0; cc < 32; cc++) {
        int c = cs * 32 + cc;
        size_t idx = (size_t)c * LTOT + l;
        float2 v = *reinterpret_cast<const float2*>(xb + idx);
        *reinterpret_cast<__half2*>(xhi + idx) = __float22half2_rn(v);
#pragma unroll
        for (int hh = 0; hh < HEADS; hh++) {
            float w = wq_s[hh * CIN + c];
            acc[hh][0] += w * v.x;
            acc[hh][1] += w * v.y;
        }
    }
#pragma unroll
    for (int hh = 0; hh < HEADS; hh++) {
        red[cs][hh][lp * 2]     = acc[hh][0];
        red[cs][hh][lp * 2 + 1] = acc[hh][1];
    }
    __syncthreads();
    for (int i = threadIdx.x; i < HEADS * 64; i += 256) {
        int hh = i >> 6, l2i = i & 63;
        float s = 0.f;
#pragma unroll
        for (int c8 = 0; c8 < 8; c8++) s += red[c8][hh][l2i];
        g_s[(size_t)(b * HEADS + hh) * LTOT + blockIdx.x * 64 + l2i] = s;
    }
}

// ---------------- K3: HMMA 2-term GEMM  C = (Ahi+Alo)·Xhi ----------------
// stage (40KB): Ahi 16K | Alo 16K | Xhi 8K; two stages = 80 KB; 2 CTAs/SM.
#define STAGE_BYTES 40960
__global__ void __launch_bounds__(256, 2) hgemm(
    const __half* __restrict__ Ahi, const __half* __restrict__ Alo,
    const __half* __restrict__ Xhi, float* __restrict__ C) {
    extern __shared__ __align__(1024) unsigned char sb[];
    const uint32_t s0 = smem_u32(sb);

    const int tid = threadIdx.x;
    const int wid = tid >> 5, lane = tid & 31;
    const int l0 = blockIdx.x * 64;
    const int m0 = blockIdx.y * 128;
    const int b  = blockIdx.z;

    const int m_base = (wid >> 1) * 32;
    const int n_base = (wid & 1) * 32;

    const __half* Xhi_b = Xhi + (size_t)b * CIN * LTOT;

    float acc[2][4][4];
#pragma unroll
    for (int mt = 0; mt < 2; mt++)
#pragma unroll
        for (int nt = 0; nt < 4; nt++)
#pragma unroll
            for (int i = 0; i < 4; i++) acc[mt][nt][i] = 0.f;

    auto load_chunk = [&](int c) {
        const int st = c & 1;
        const int k0 = c * 64;
        uint32_t dAhi = s0 + st * STAGE_BYTES;
        uint32_t dAlo = dAhi + 16384;
        uint32_t dXhi = dAhi + 32768;
#pragma unroll
        for (int j = 0; j < 4; j++) {
            int idx = tid + j * 256;
            int row = idx >> 3, ch = idx & 7;
            uint32_t off = sw128(row * 128 + ch * 16);
            size_t gidx = (size_t)(m0 + row) * CIN + k0 + ch * 8;
            cp16(dAhi + off, Ahi + gidx);
            cp16(dAlo + off, Alo + gidx);
        }
#pragma unroll
        for (int j = 0; j < 2; j++) {
            int idx = tid + j * 256;
            int row = idx >> 3, ch = idx & 7;
            uint32_t off = sw128(row * 128 + ch * 16);
            cp16(dXhi + off, Xhi_b + (size_t)(k0 + row) * LTOT + l0 + ch * 8);
        }
        CP_COMMIT();
    };

    load_chunk(0);
    const int b3 = lane >> 3, r8 = lane & 7;

    for (int c = 0; c < 4; c++) {
        if (c + 1 < 4) {
            load_chunk(c + 1);
            asm volatile("cp.async.wait_group 1;" ::: "memory");
        } else {
            asm volatile("cp.async.wait_group 0;" ::: "memory");
        }
        __syncthreads();

        const int st = c & 1;
        const uint32_t sAhi = s0 + st * STAGE_BYTES;
        const uint32_t sAlo = sAhi + 16384;
        const uint32_t sXhi = sAhi + 32768;

#pragma unroll
        for (int kk = 0; kk < 4; kk++) {
            uint32_t ahi[2][4], alo[2][4], bhi[2][4];
#pragma unroll
            for (int mt = 0; mt < 2; mt++) {
                int row = m_base + mt * 16 + ((b3 & 1) << 3) + r8;
                uint32_t byte = sw128((uint32_t)(row * 128 + kk * 32 + ((b3 >> 1) << 4)));
                ldmA4(ahi[mt], sAhi + byte);
                ldmA4(alo[mt], sAlo + byte);
            }
#pragma unroll
            for (int g = 0; g < 2; g++) {
                int krow = kk * 16 + (lane & 15);
                int ncol = n_base + g * 16 + ((lane >> 4) << 3);
                uint32_t byte = sw128((uint32_t)(krow * 128 + ncol * 2));
                ldmBt4(bhi[g], sXhi + byte);
            }
#pragma unroll
            for (int mt = 0; mt < 2; mt++)
#pragma unroll
                for (int g = 0; g < 2; g++)
#pragma unroll
                    for (int h = 0; h < 2; h++) {
                        float* a = acc[mt][g * 2 + h];
                        hmma(a, ahi[mt], &bhi[g][h * 2]);   // hh
                        hmma(a, alo[mt], &bhi[g][h * 2]);   // lh
                    }
        }
        __syncthreads();
    }

    const int g = lane >> 2, j2 = (lane & 3) * 2;
    float* Cb = C + (size_t)b * DMODEL * LTOT;
#pragma unroll
    for (int mt = 0; mt < 2; mt++) {
        int mrow = m0 + m_base + mt * 16 + g;
#pragma unroll
        for (int nt = 0; nt < 4; nt++) {
            int col = l0 + n_base + nt * 8 + j2;
            *reinterpret_cast<float2*>(Cb + (size_t)mrow * LTOT + col) =
                make_float2(acc[mt][nt][0], acc[mt][nt][1]);
            *reinterpret_cast<float2*>(Cb + (size_t)(mrow + 8) * LTOT + col) =
                make_float2(acc[mt][nt][2], acc[mt][nt][3]);
        }
    }
}

// ---------------- K4: fused softmax + AV gather, fp16 output ----------------
__global__ void __launch_bounds__(256) attn_av_kernel(
    const float* __restrict__ pos_emb, const float* __restrict__ Wlin) {
    __shared__ float sm_at[KWIN][64];
    const int bh = blockIdx.y;
    const int b = bh >> 3, h = bh & 7;
    const int l0 = blockIdx.x * 64;
    const int tid = threadIdx.x;

    if (tid < 64) {
        float scale = Wlin[0] + Wlin[1] + Wlin[2] + Wlin[3];
        int l = l0 + tid;
        int y = l / HDIM, xx = l % HDIM;
        const float* sp = g_s + (size_t)bh * LTOT;
        float logit[KWIN];
#pragma unroll
        for (int kh = 0; kh < 3; kh++)
#pragma unroll
            for (int kw = 0; kw < 3; kw++) {
                int yy = y + kh - 1, xz = xx + kw - 1;
                float sv = (yy >= 0 && yy < HDIM && xz >= 0 && xz < HDIM)
                               ? sp[yy * HDIM + xz] : 0.f;
                logit[kh * 3 + kw] = sv + pos_emb[kh + kw];
            }
        float m = logit[0];
#pragma unroll
        for (int k = 1; k < KWIN; k++) m = fmaxf(m, logit[k]);
        float e[KWIN], sum = 0.f;
#pragma unroll
        for (int k = 0; k < KWIN; k++) { e[k] = __expf(logit[k] - m); sum += e[k]; }
        float inv = scale / sum;
#pragma unroll
        for (int k = 0; k < KWIN; k++) sm_at[k][tid] = e[k] * inv;
    }
    __syncthreads();

    const int lp = tid & 31;
    const int dg = tid >> 5;
    float att[2][KWIN];
    int off[2][KWIN];
#pragma unroll
    for (int e = 0; e < 2; e++) {
        int ll = lp * 2 + e;
        int l = l0 + ll;
        int y = l / HDIM, xx = l % HDIM;
#pragma unroll
        for (int kh = 0; kh < 3; kh++)
#pragma unroll
            for (int kw = 0; kw < 3; kw++) {
                int k = kh * 3 + kw;
                int yy = y + kh - 1, xz = xx + kw - 1;
                bool ok = (yy >= 0 && yy < HDIM && xz >= 0 && xz < HDIM);
                att[e][k] = ok ? sm_at[k][ll] : 0.f;
                off[e][k] = ok ? yy * HDIM + xz : 0;
            }
    }
    const size_t base = (size_t)(b * DMODEL + h * NPH + dg * 4) * LTOT;
#pragma unroll
    for (int dd = 0; dd < 4; dd++) {
        const float* vp = g_v + base + (size_t)dd * LTOT;
        float o[2];
#pragma unroll
        for (int e = 0; e < 2; e++) {
            float a = 0.f;
#pragma unroll
            for (int k = 0; k < KWIN; k++) a += att[e][k] * vp[off[e][k]];
            o[e] = a;
        }
        size_t oidx = base + (size_t)dd * LTOT + l0 + lp * 2;
        *reinterpret_cast<__half2*>(g_ohi + oidx) =
            __float22half2_rn(make_float2(o[0], o[1]));
    }
}

// ---------------- host launcher ----------------
extern "C" void kernel_launch(void* const* d_in, const int* in_sizes, int n_in,
                              void* d_out, int out_size) {
    const float* x       = (const float*)d_in[0];
    const float* q       = (const float*)d_in[1];
    const float* Wk      = (const float*)d_in[2];
    const float* Wv      = (const float*)d_in[3];
    const float* pos_emb = (const float*)d_in[4];
    const float* Wlin    = (const float*)d_in[5];
    const float* Wproj   = (const float*)d_in[6];
    float* out = (float*)d_out;

    void *pv, *pxhi, *pohi, *pwvhi, *pwvlo, *pwphi, *pwplo;
    cudaGetSymbolAddress(&pv, g_v);
    cudaGetSymbolAddress(&pxhi, g_xhi);
    cudaGetSymbolAddress(&pohi, g_ohi);
    cudaGetSymbolAddress(&pwvhi, g_wvhi);
    cudaGetSymbolAddress(&pwvlo, g_wvlo);
    cudaGetSymbolAddress(&pwphi, g_wphi);
    cudaGetSymbolAddress(&pwplo, g_wplo);

    static bool attr_set = false;
    if (!attr_set) {
        cudaFuncSetAttribute(hgemm, cudaFuncAttributeMaxDynamicSharedMemorySize,
                             2 * STAGE_BYTES);
        attr_set = true;
    }

    const int WN4 = DMODEL * CIN / 4;
    const int SMEM = 2 * STAGE_BYTES;

    wq_kernel<<<BATCH * HEADS, 256>>>(q, Wk);
    split_kernel<<<(WN4 + 255) / 256, 256>>>(Wv, (__half*)pwvhi, (__half*)pwvlo, WN4);
    split_kernel<<<(WN4 + 255) / 256, 256>>>(Wproj, (__half*)pwphi, (__half*)pwplo, WN4);
    s_split_kernel<<<dim3(LTOT / 64, BATCH), 256>>>(x);

    hgemm<<<dim3(LTOT / 64, DMODEL / 128, BATCH), 256, SMEM>>>(
        (const __half*)pwvhi, (const __half*)pwvlo,
        (const __half*)pxhi, (float*)pv);

    attn_av_kernel<<<dim3(LTOT / 64, BATCH * HEADS), 256>>>(pos_emb, Wlin);

    hgemm<<<dim3(LTOT / 64, DMODEL / 128, BATCH), 256, SMEM>>>(
        (const __half*)pwphi, (const __half*)pwplo,
        (const __half*)pohi, out);
}

// round 10
// speedup vs baseline: 1.5853x; 1.1193x over previous
#include <cuda_runtime.h>
#include <cuda_fp16.h>
#include <cstdint>

#define BATCH 16
#define CIN   256
#define DMODEL 256
#define HEADS 8
#define NPH   32
#define HDIM  56
#define LTOT  3136
#define KWIN  9

// ---------------- device scratch ----------------
__device__ float g_wq[BATCH * HEADS * CIN];
__device__ float g_s[BATCH * HEADS * LTOT];
__device__ __align__(16) __half g_v[BATCH * DMODEL * LTOT];
__device__ __align__(16) __half g_xhi[BATCH * CIN * LTOT];
__device__ __align__(16) __half g_ohi[BATCH * DMODEL * LTOT];
__device__ __align__(16) __half g_wvhi[DMODEL * CIN];
__device__ __align__(16) __half g_wphi[DMODEL * DMODEL];
__device__ __align__(16) __half g_wplo[DMODEL * DMODEL];

// ---------------- PTX helpers ----------------
__device__ __forceinline__ uint32_t smem_u32(const void* p) {
    uint32_t a;
    asm("{ .reg .u64 t; cvta.to.shared.u64 t, %1; cvt.u32.u64 %0, t; }" : "=r"(a) : "l"(p));
    return a;
}
__device__ __forceinline__ void ldmA4(uint32_t* r, uint32_t addr) {
    asm volatile("ldmatrix.sync.aligned.m8n8.x4.shared.b16 {%0,%1,%2,%3}, [%4];"
                 : "=r"(r[0]), "=r"(r[1]), "=r"(r[2]), "=r"(r[3]) : "r"(addr));
}
__device__ __forceinline__ void ldmBt4(uint32_t* r, uint32_t addr) {
    asm volatile("ldmatrix.sync.aligned.m8n8.x4.trans.shared.b16 {%0,%1,%2,%3}, [%4];"
                 : "=r"(r[0]), "=r"(r[1]), "=r"(r[2]), "=r"(r[3]) : "r"(addr));
}
__device__ __forceinline__ void hmma(float* d, const uint32_t* a, const uint32_t* b) {
    asm volatile("mma.sync.aligned.m16n8k16.row.col.f32.f16.f16.f32 "
                 "{%0,%1,%2,%3}, {%4,%5,%6,%7}, {%8,%9}, {%0,%1,%2,%3};"
                 : "+f"(d[0]), "+f"(d[1]), "+f"(d[2]), "+f"(d[3])
                 : "r"(a[0]), "r"(a[1]), "r"(a[2]), "r"(a[3]), "r"(b[0]), "r"(b[1]));
}
__device__ __forceinline__ void cp16(uint32_t dst, const void* src) {
    asm volatile("cp.async.cg.shared.global [%0], [%1], 16;" :: "r"(dst), "l"(src));
}
#define CP_COMMIT() asm volatile("cp.async.commit_group;" ::: "memory")
__device__ __forceinline__ uint32_t sw128(uint32_t b) { return b ^ ((b >> 3) & 0x70); }

// ---------------- K0: hi/lo fp16 split (weights) ----------------
__global__ void split_kernel(const float* __restrict__ src, __half* __restrict__ hi,
                             __half* __restrict__ lo, int n4) {
    int i = blockIdx.x * 256 + threadIdx.x;
    if (i >= n4) return;
    float4 v = reinterpret_cast<const float4*>(src)[i];
    float vv[4] = {v.x, v.y, v.z, v.w};
    __half h[4], l[4];
#pragma unroll
    for (int j = 0; j < 4; j++) {
        h[j] = __float2half(vv[j]);
        l[j] = __float2half(vv[j] - __half2float(h[j]));
    }
    __half2* H = reinterpret_cast<__half2*>(hi);
    H[2 * i]     = __half2(h[0], h[1]);
    H[2 * i + 1] = __half2(h[2], h[3]);
    if (lo) {
        __half2* L = reinterpret_cast<__half2*>(lo);
        L[2 * i]     = __half2(l[0], l[1]);
        L[2 * i + 1] = __half2(l[2], l[3]);
    }
}

// ---------------- K1: wq[b,h,c] = sum_n q[b,h*32+n] * Wk[h*32+n, c] ----------------
__global__ void wq_kernel(const float* __restrict__ q, const float* __restrict__ Wk) {
    int bh = blockIdx.x;
    int b = bh >> 3, h = bh & 7;
    __shared__ float qs[NPH];
    if (threadIdx.x < NPH) qs[threadIdx.x] = q[b * DMODEL + h * NPH + threadIdx.x];
    __syncthreads();
    int c = threadIdx.x;
    float acc = 0.f;
#pragma unroll
    for (int n = 0; n < NPH; n++) acc += qs[n] * Wk[(h * NPH + n) * CIN + c];
    g_wq[bh * CIN + c] = acc;
}

// ---------------- K2: s + x fp16 cast fused ----------------
__global__ void __launch_bounds__(256) s_split_kernel(const float* __restrict__ x) {
    __shared__ float wq_s[HEADS * CIN];
    __shared__ float red[8][HEADS][64];
    const int b = blockIdx.y;
    {
        const float4* src = reinterpret_cast<const float4*>(g_wq + b * HEADS * CIN);
        float4* dst = reinterpret_cast<float4*>(wq_s);
        for (int i = threadIdx.x; i < HEADS * CIN / 4; i += 256) dst[i] = src[i];
    }
    __syncthreads();

    const int lp = threadIdx.x & 31;
    const int cs = threadIdx.x >> 5;
    const int l = blockIdx.x * 64 + lp * 2;
    const float* xb = x + (size_t)b * CIN * LTOT;
    __half* xhi = g_xhi + (size_t)b * CIN * LTOT;

    float acc[HEADS][2] = {};
#pragma unroll 8
    for (int cc = 0; cc < 32; cc++) {
        int c = cs * 32 + cc;
        size_t idx = (size_t)c * LTOT + l;
        float2 v = *reinterpret_cast<const float2*>(xb + idx);
        *reinterpret_cast<__half2*>(xhi + idx) = __float22half2_rn(v);
#pragma unroll
        for (int hh = 0; hh < HEADS; hh++) {
            float w = wq_s[hh * CIN + c];
            acc[hh][0] += w * v.x;
            acc[hh][1] += w * v.y;
        }
    }
#pragma unroll
    for (int hh = 0; hh < HEADS; hh++) {
        red[cs][hh][lp * 2]     = acc[hh][0];
        red[cs][hh][lp * 2 + 1] = acc[hh][1];
    }
    __syncthreads();
    for (int i = threadIdx.x; i < HEADS * 64; i += 256) {
        int hh = i >> 6, l2i = i & 63;
        float s = 0.f;
#pragma unroll
        for (int c8 = 0; c8 < 8; c8++) s += red[c8][hh][l2i];
        g_s[(size_t)(b * HEADS + hh) * LTOT + blockIdx.x * 64 + l2i] = s;
    }
}

// ---------------- K3: HMMA GEMM, templated terms + output type ----------------
// TERMS=2: C=(Ahi+Alo)*Xhi, stage 40KB. TERMS=1: C=Ahi*Xhi, stage 24KB.
template <int TERMS, typename OutT>
__global__ void __launch_bounds__(256, 2) hgemm(
    const __half* __restrict__ Ahi, const __half* __restrict__ Alo,
    const __half* __restrict__ Xhi, OutT* __restrict__ C) {
    constexpr uint32_t STG = (TERMS == 2) ? 40960u : 24576u;
    constexpr uint32_t XOFF = (TERMS == 2) ? 32768u : 16384u;
    extern __shared__ __align__(1024) unsigned char sb[];
    const uint32_t s0 = smem_u32(sb);

    const int tid = threadIdx.x;
    const int wid = tid >> 5, lane = tid & 31;
    const int l0 = blockIdx.x * 64;
    const int m0 = blockIdx.y * 128;
    const int b  = blockIdx.z;

    const int m_base = (wid >> 1) * 32;
    const int n_base = (wid & 1) * 32;

    const __half* Xhi_b = Xhi + (size_t)b * CIN * LTOT;

    float acc[2][4][4];
#pragma unroll
    for (int mt = 0; mt < 2; mt++)
#pragma unroll
        for (int nt = 0; nt < 4; nt++)
#pragma unroll
            for (int i = 0; i < 4; i++) acc[mt][nt][i] = 0.f;

    auto load_chunk = [&](int c) {
        const int st = c & 1;
        const int k0 = c * 64;
        uint32_t dAhi = s0 + st * STG;
        uint32_t dXhi = dAhi + XOFF;
#pragma unroll
        for (int j = 0; j < 4; j++) {
            int idx = tid + j * 256;
            int row = idx >> 3, ch = idx & 7;
            uint32_t off = sw128(row * 128 + ch * 16);
            size_t gidx = (size_t)(m0 + row) * CIN + k0 + ch * 8;
            cp16(dAhi + off, Ahi + gidx);
            if (TERMS == 2) cp16(dAhi + 16384 + off, Alo + gidx);
        }
#pragma unroll
        for (int j = 0; j < 2; j++) {
            int idx = tid + j * 256;
            int row = idx >> 3, ch = idx & 7;
            uint32_t off = sw128(row * 128 + ch * 16);
            cp16(dXhi + off, Xhi_b + (size_t)(k0 + row) * LTOT + l0 + ch * 8);
        }
        CP_COMMIT();
    };

    load_chunk(0);
    const int b3 = lane >> 3, r8 = lane & 7;

    for (int c = 0; c < 4; c++) {
        if (c + 1 < 4) {
            load_chunk(c + 1);
            asm volatile("cp.async.wait_group 1;" ::: "memory");
        } else {
            asm volatile("cp.async.wait_group 0;" ::: "memory");
        }
        __syncthreads();

        const int st = c & 1;
        const uint32_t sAhi = s0 + st * STG;
        const uint32_t sAlo = sAhi + 16384;
        const uint32_t sXhi = sAhi + XOFF;

#pragma unroll
        for (int kk = 0; kk < 4; kk++) {
            uint32_t ahi[2][4], alo[2][4], bhi[2][4];
#pragma unroll
            for (int mt = 0; mt < 2; mt++) {
                int row = m_base + mt * 16 + ((b3 & 1) << 3) + r8;
                uint32_t byte = sw128((uint32_t)(row * 128 + kk * 32 + ((b3 >> 1) << 4)));
                ldmA4(ahi[mt], sAhi + byte);
                if (TERMS == 2) ldmA4(alo[mt], sAlo + byte);
            }
#pragma unroll
            for (int g = 0; g < 2; g++) {
                int krow = kk * 16 + (lane & 15);
                int ncol = n_base + g * 16 + ((lane >> 4) << 3);
                uint32_t byte = sw128((uint32_t)(krow * 128 + ncol * 2));
                ldmBt4(bhi[g], sXhi + byte);
            }
#pragma unroll
            for (int mt = 0; mt < 2; mt++)
#pragma unroll
                for (int g = 0; g < 2; g++)
#pragma unroll
                    for (int h = 0; h < 2; h++) {
                        float* a = acc[mt][g * 2 + h];
                        hmma(a, ahi[mt], &bhi[g][h * 2]);
                        if (TERMS == 2) hmma(a, alo[mt], &bhi[g][h * 2]);
                    }
        }
        __syncthreads();
    }

    const int g = lane >> 2, j2 = (lane & 3) * 2;
    OutT* Cb = C + (size_t)b * DMODEL * LTOT;
#pragma unroll
    for (int mt = 0; mt < 2; mt++) {
        int mrow = m0 + m_base + mt * 16 + g;
#pragma unroll
        for (int nt = 0; nt < 4; nt++) {
            int col = l0 + n_base + nt * 8 + j2;
            if constexpr (sizeof(OutT) == 4) {
                *reinterpret_cast<float2*>(Cb + (size_t)mrow * LTOT + col) =
                    make_float2(acc[mt][nt][0], acc[mt][nt][1]);
                *reinterpret_cast<float2*>(Cb + (size_t)(mrow + 8) * LTOT + col) =
                    make_float2(acc[mt][nt][2], acc[mt][nt][3]);
            } else {
                *reinterpret_cast<__half2*>(Cb + (size_t)mrow * LTOT + col) =
                    __float22half2_rn(make_float2(acc[mt][nt][0], acc[mt][nt][1]));
                *reinterpret_cast<__half2*>(Cb + (size_t)(mrow + 8) * LTOT + col) =
                    __float22half2_rn(make_float2(acc[mt][nt][2], acc[mt][nt][3]));
            }
        }
    }
}

// ---------------- K4: fused softmax + AV gather (fp16 v), fp16 output ----------------
__global__ void __launch_bounds__(256) attn_av_kernel(
    const float* __restrict__ pos_emb, const float* __restrict__ Wlin) {
    __shared__ float sm_at[KWIN][64];
    const int bh = blockIdx.y;
    const int b = bh >> 3, h = bh & 7;
    const int l0 = blockIdx.x * 64;
    const int tid = threadIdx.x;

    if (tid < 64) {
        float scale = Wlin[0] + Wlin[1] + Wlin[2] + Wlin[3];
        int l = l0 + tid;
        int y = l / HDIM, xx = l % HDIM;
        const float* sp = g_s + (size_t)bh * LTOT;
        float logit[KWIN];
#pragma unroll
        for (int kh = 0; kh < 3; kh++)
#pragma unroll
            for (int kw = 0; kw < 3; kw++) {
                int yy = y + kh - 1, xz = xx + kw - 1;
                float sv = (yy >= 0 && yy < HDIM && xz >= 0 && xz < HDIM)
                               ? sp[yy * HDIM + xz] : 0.f;
                logit[kh * 3 + kw] = sv + pos_emb[kh + kw];
            }
        float m = logit[0];
#pragma unroll
        for (int k = 1; k < KWIN; k++) m = fmaxf(m, logit[k]);
        float e[KWIN], sum = 0.f;
#pragma unroll
        for (int k = 0; k < KWIN; k++) { e[k] = __expf(logit[k] - m); sum += e[k]; }
        float inv = scale / sum;
#pragma unroll
        for (int k = 0; k < KWIN; k++) sm_at[k][tid] = e[k] * inv;
    }
    __syncthreads();

    const int lp = tid & 31;
    const int dg = tid >> 5;
    float att[2][KWIN];
    int off[2][KWIN];
#pragma unroll
    for (int e = 0; e < 2; e++) {
        int ll = lp * 2 + e;
        int l = l0 + ll;
        int y = l / HDIM, xx = l % HDIM;
#pragma unroll
        for (int kh = 0; kh < 3; kh++)
#pragma unroll
            for (int kw = 0; kw < 3; kw++) {
                int k = kh * 3 + kw;
                int yy = y + kh - 1, xz = xx + kw - 1;
                bool ok = (yy >= 0 && yy < HDIM && xz >= 0 && xz < HDIM);
                att[e][k] = ok ? sm_at[k][ll] : 0.f;
                off[e][k] = ok ? yy * HDIM + xz : 0;
            }
    }
    const size_t base = (size_t)(b * DMODEL + h * NPH + dg * 4) * LTOT;
#pragma unroll
    for (int dd = 0; dd < 4; dd++) {
        const __half* vp = g_v + base + (size_t)dd * LTOT;
        float o[2];
#pragma unroll
        for (int e = 0; e < 2; e++) {
            float a = 0.f;
#pragma unroll
            for (int k = 0; k < KWIN; k++)
                a += att[e][k] * __half2float(vp[off[e][k]]);
            o[e] = a;
        }
        size_t oidx = base + (size_t)dd * LTOT + l0 + lp * 2;
        *reinterpret_cast<__half2*>(g_ohi + oidx) =
            __float22half2_rn(make_float2(o[0], o[1]));
    }
}

// ---------------- host launcher ----------------
extern "C" void kernel_launch(void* const* d_in, const int* in_sizes, int n_in,
                              void* d_out, int out_size) {
    const float* x       = (const float*)d_in[0];
    const float* q       = (const float*)d_in[1];
    const float* Wk      = (const float*)d_in[2];
    const float* Wv      = (const float*)d_in[3];
    const float* pos_emb = (const float*)d_in[4];
    const float* Wlin    = (const float*)d_in[5];
    const float* Wproj   = (const float*)d_in[6];
    float* out = (float*)d_out;

    void *pv, *pxhi, *pohi, *pwvhi, *pwphi, *pwplo;
    cudaGetSymbolAddress(&pv, g_v);
    cudaGetSymbolAddress(&pxhi, g_xhi);
    cudaGetSymbolAddress(&pohi, g_ohi);
    cudaGetSymbolAddress(&pwvhi, g_wvhi);
    cudaGetSymbolAddress(&pwphi, g_wphi);
    cudaGetSymbolAddress(&pwplo, g_wplo);

    static bool attr_set = false;
    if (!attr_set) {
        cudaFuncSetAttribute(hgemm<1, __half>,
                             cudaFuncAttributeMaxDynamicSharedMemorySize, 2 * 24576);
        cudaFuncSetAttribute(hgemm<2, float>,
                             cudaFuncAttributeMaxDynamicSharedMemorySize, 2 * 40960);
        attr_set = true;
    }

    const int WN4 = DMODEL * CIN / 4;

    wq_kernel<<<BATCH * HEADS, 256>>>(q, Wk);
    split_kernel<<<(WN4 + 255) / 256, 256>>>(Wv, (__half*)pwvhi, nullptr, WN4);
    split_kernel<<<(WN4 + 255) / 256, 256>>>(Wproj, (__half*)pwphi, (__half*)pwplo, WN4);
    s_split_kernel<<<dim3(LTOT / 64, BATCH), 256>>>(x);

    hgemm<1, __half><<<dim3(LTOT / 64, DMODEL / 128, BATCH), 256, 2 * 24576>>>(
        (const __half*)pwvhi, nullptr, (const __half*)pxhi, (__half*)pv);

    attn_av_kernel<<<dim3(LTOT / 64, BATCH * HEADS), 256>>>(pos_emb, Wlin);

    hgemm<2, float><<<dim3(LTOT / 64, DMODEL / 128, BATCH), 256, 2 * 40960>>>(
        (const __half*)pwphi, (const __half*)pwplo, (const __half*)pohi, out);
}

// round 11
// speedup vs baseline: 1.7394x; 1.0972x over previous
#include <cuda_runtime.h>
#include <cuda_fp16.h>
#include <cstdint>

#define BATCH 16
#define CIN   256
#define DMODEL 256
#define HEADS 8
#define NPH   32
#define HDIM  56
#define LTOT  3136
#define KWIN  9

// ---------------- device scratch ----------------
__device__ float g_wq[BATCH * HEADS * CIN];
__device__ float g_s[BATCH * HEADS * LTOT];
__device__ __align__(16) __half g_v[BATCH * DMODEL * LTOT];
__device__ __align__(16) __half g_xhi[BATCH * CIN * LTOT];
__device__ __align__(16) __half g_ohi[BATCH * DMODEL * LTOT];
__device__ __align__(16) __half g_wvhi[DMODEL * CIN];
__device__ __align__(16) __half g_wphi[DMODEL * DMODEL];

// ---------------- PTX helpers ----------------
__device__ __forceinline__ uint32_t smem_u32(const void* p) {
    uint32_t a;
    asm("{ .reg .u64 t; cvta.to.shared.u64 t, %1; cvt.u32.u64 %0, t; }" : "=r"(a) : "l"(p));
    return a;
}
__device__ __forceinline__ void ldmA4(uint32_t* r, uint32_t addr) {
    asm volatile("ldmatrix.sync.aligned.m8n8.x4.shared.b16 {%0,%1,%2,%3}, [%4];"
                 : "=r"(r[0]), "=r"(r[1]), "=r"(r[2]), "=r"(r[3]) : "r"(addr));
}
__device__ __forceinline__ void ldmBt4(uint32_t* r, uint32_t addr) {
    asm volatile("ldmatrix.sync.aligned.m8n8.x4.trans.shared.b16 {%0,%1,%2,%3}, [%4];"
                 : "=r"(r[0]), "=r"(r[1]), "=r"(r[2]), "=r"(r[3]) : "r"(addr));
}
__device__ __forceinline__ void hmma(float* d, const uint32_t* a, const uint32_t* b) {
    asm volatile("mma.sync.aligned.m16n8k16.row.col.f32.f16.f16.f32 "
                 "{%0,%1,%2,%3}, {%4,%5,%6,%7}, {%8,%9}, {%0,%1,%2,%3};"
                 : "+f"(d[0]), "+f"(d[1]), "+f"(d[2]), "+f"(d[3])
                 : "r"(a[0]), "r"(a[1]), "r"(a[2]), "r"(a[3]), "r"(b[0]), "r"(b[1]));
}
__device__ __forceinline__ void cp16(uint32_t dst, const void* src) {
    asm volatile("cp.async.cg.shared.global [%0], [%1], 16;" :: "r"(dst), "l"(src));
}
#define CP_COMMIT() asm volatile("cp.async.commit_group;" ::: "memory")
__device__ __forceinline__ uint32_t sw128(uint32_t b) { return b ^ ((b >> 3) & 0x70); }

// ---------------- K0: fp16 split / cast (weights) ----------------
__global__ void split_kernel(const float* __restrict__ src, __half* __restrict__ hi,
                             __half* __restrict__ lo, int n4) {
    int i = blockIdx.x * 256 + threadIdx.x;
    if (i >= n4) return;
    float4 v = reinterpret_cast<const float4*>(src)[i];
    float vv[4] = {v.x, v.y, v.z, v.w};
    __half h[4], l[4];
#pragma unroll
    for (int j = 0; j < 4; j++) {
        h[j] = __float2half(vv[j]);
        l[j] = __float2half(vv[j] - __half2float(h[j]));
    }
    __half2* H = reinterpret_cast<__half2*>(hi);
    H[2 * i]     = __half2(h[0], h[1]);
    H[2 * i + 1] = __half2(h[2], h[3]);
    if (lo) {
        __half2* L = reinterpret_cast<__half2*>(lo);
        L[2 * i]     = __half2(l[0], l[1]);
        L[2 * i + 1] = __half2(l[2], l[3]);
    }
}

// ---------------- K1: wq[b,h,c] = sum_n q[b,h*32+n] * Wk[h*32+n, c] ----------------
__global__ void wq_kernel(const float* __restrict__ q, const float* __restrict__ Wk) {
    int bh = blockIdx.x;
    int b = bh >> 3, h = bh & 7;
    __shared__ float qs[NPH];
    if (threadIdx.x < NPH) qs[threadIdx.x] = q[b * DMODEL + h * NPH + threadIdx.x];
    __syncthreads();
    int c = threadIdx.x;
    float acc = 0.f;
#pragma unroll
    for (int n = 0; n < NPH; n++) acc += qs[n] * Wk[(h * NPH + n) * CIN + c];
    g_wq[bh * CIN + c] = acc;
}

// ---------------- K2: s + x fp16 cast fused ----------------
__global__ void __launch_bounds__(256) s_split_kernel(const float* __restrict__ x) {
    __shared__ float wq_s[HEADS * CIN];
    __shared__ float red[8][HEADS][64];
    const int b = blockIdx.y;
    {
        const float4* src = reinterpret_cast<const float4*>(g_wq + b * HEADS * CIN);
        float4* dst = reinterpret_cast<float4*>(wq_s);
        for (int i = threadIdx.x; i < HEADS * CIN / 4; i += 256) dst[i] = src[i];
    }
    __syncthreads();

    const int lp = threadIdx.x & 31;
    const int cs = threadIdx.x >> 5;
    const int l = blockIdx.x * 64 + lp * 2;
    const float* xb = x + (size_t)b * CIN * LTOT;
    __half* xhi = g_xhi + (size_t)b * CIN * LTOT;

    float acc[HEADS][2] = {};
#pragma unroll 8
    for (int cc = 0; cc < 32; cc++) {
        int c = cs * 32 + cc;
        size_t idx = (size_t)c * LTOT + l;
        float2 v = *reinterpret_cast<const float2*>(xb + idx);
        *reinterpret_cast<__half2*>(xhi + idx) = __float22half2_rn(v);
#pragma unroll
        for (int hh = 0; hh < HEADS; hh++) {
            float w = wq_s[hh * CIN + c];
            acc[hh][0] += w * v.x;
            acc[hh][1] += w * v.y;
        }
    }
#pragma unroll
    for (int hh = 0; hh < HEADS; hh++) {
        red[cs][hh][lp * 2]     = acc[hh][0];
        red[cs][hh][lp * 2 + 1] = acc[hh][1];
    }
    __syncthreads();
    for (int i = threadIdx.x; i < HEADS * 64; i += 256) {
        int hh = i >> 6, l2i = i & 63;
        float s = 0.f;
#pragma unroll
        for (int c8 = 0; c8 < 8; c8++) s += red[c8][hh][l2i];
        g_s[(size_t)(b * HEADS + hh) * LTOT + blockIdx.x * 64 + l2i] = s;
    }
}

// ---------------- K3: HMMA GEMM, templated terms + output type ----------------
template <int TERMS, typename OutT>
__global__ void __launch_bounds__(256, 2) hgemm(
    const __half* __restrict__ Ahi, const __half* __restrict__ Alo,
    const __half* __restrict__ Xhi, OutT* __restrict__ C) {
    constexpr uint32_t STG = (TERMS == 2) ? 40960u : 24576u;
    constexpr uint32_t XOFF = (TERMS == 2) ? 32768u : 16384u;
    extern __shared__ __align__(1024) unsigned char sb[];
    const uint32_t s0 = smem_u32(sb);

    const int tid = threadIdx.x;
    const int wid = tid >> 5, lane = tid & 31;
    const int l0 = blockIdx.x * 64;
    const int m0 = blockIdx.y * 128;
    const int b  = blockIdx.z;

    const int m_base = (wid >> 1) * 32;
    const int n_base = (wid & 1) * 32;

    const __half* Xhi_b = Xhi + (size_t)b * CIN * LTOT;

    float acc[2][4][4];
#pragma unroll
    for (int mt = 0; mt < 2; mt++)
#pragma unroll
        for (int nt = 0; nt < 4; nt++)
#pragma unroll
            for (int i = 0; i < 4; i++) acc[mt][nt][i] = 0.f;

    auto load_chunk = [&](int c) {
        const int st = c & 1;
        const int k0 = c * 64;
        uint32_t dAhi = s0 + st * STG;
        uint32_t dXhi = dAhi + XOFF;
#pragma unroll
        for (int j = 0; j < 4; j++) {
            int idx = tid + j * 256;
            int row = idx >> 3, ch = idx & 7;
            uint32_t off = sw128(row * 128 + ch * 16);
            size_t gidx = (size_t)(m0 + row) * CIN + k0 + ch * 8;
            cp16(dAhi + off, Ahi + gidx);
            if (TERMS == 2) cp16(dAhi + 16384 + off, Alo + gidx);
        }
#pragma unroll
        for (int j = 0; j < 2; j++) {
            int idx = tid + j * 256;
            int row = idx >> 3, ch = idx & 7;
            uint32_t off = sw128(row * 128 + ch * 16);
            cp16(dXhi + off, Xhi_b + (size_t)(k0 + row) * LTOT + l0 + ch * 8);
        }
        CP_COMMIT();
    };

    load_chunk(0);
    const int b3 = lane >> 3, r8 = lane & 7;

    for (int c = 0; c < 4; c++) {
        if (c + 1 < 4) {
            load_chunk(c + 1);
            asm volatile("cp.async.wait_group 1;" ::: "memory");
        } else {
            asm volatile("cp.async.wait_group 0;" ::: "memory");
        }
        __syncthreads();

        const int st = c & 1;
        const uint32_t sAhi = s0 + st * STG;
        const uint32_t sAlo = sAhi + 16384;
        const uint32_t sXhi = sAhi + XOFF;

#pragma unroll
        for (int kk = 0; kk < 4; kk++) {
            uint32_t ahi[2][4], alo[2][4], bhi[2][4];
#pragma unroll
            for (int mt = 0; mt < 2; mt++) {
                int row = m_base + mt * 16 + ((b3 & 1) << 3) + r8;
                uint32_t byte = sw128((uint32_t)(row * 128 + kk * 32 + ((b3 >> 1) << 4)));
                ldmA4(ahi[mt], sAhi + byte);
                if (TERMS == 2) ldmA4(alo[mt], sAlo + byte);
            }
#pragma unroll
            for (int g = 0; g < 2; g++) {
                int krow = kk * 16 + (lane & 15);
                int ncol = n_base + g * 16 + ((lane >> 4) << 3);
                uint32_t byte = sw128((uint32_t)(krow * 128 + ncol * 2));
                ldmBt4(bhi[g], sXhi + byte);
            }
#pragma unroll
            for (int mt = 0; mt < 2; mt++)
#pragma unroll
                for (int g = 0; g < 2; g++)
#pragma unroll
                    for (int h = 0; h < 2; h++) {
                        float* a = acc[mt][g * 2 + h];
                        hmma(a, ahi[mt], &bhi[g][h * 2]);
                        if (TERMS == 2) hmma(a, alo[mt], &bhi[g][h * 2]);
                    }
        }
        __syncthreads();
    }

    const int g = lane >> 2, j2 = (lane & 3) * 2;
    OutT* Cb = C + (size_t)b * DMODEL * LTOT;
#pragma unroll
    for (int mt = 0; mt < 2; mt++) {
        int mrow = m0 + m_base + mt * 16 + g;
#pragma unroll
        for (int nt = 0; nt < 4; nt++) {
            int col = l0 + n_base + nt * 8 + j2;
            if constexpr (sizeof(OutT) == 4) {
                *reinterpret_cast<float2*>(Cb + (size_t)mrow * LTOT + col) =
                    make_float2(acc[mt][nt][0], acc[mt][nt][1]);
                *reinterpret_cast<float2*>(Cb + (size_t)(mrow + 8) * LTOT + col) =
                    make_float2(acc[mt][nt][2], acc[mt][nt][3]);
            } else {
                *reinterpret_cast<__half2*>(Cb + (size_t)mrow * LTOT + col) =
                    __float22half2_rn(make_float2(acc[mt][nt][0], acc[mt][nt][1]));
                *reinterpret_cast<__half2*>(Cb + (size_t)(mrow + 8) * LTOT + col) =
                    __float22half2_rn(make_float2(acc[mt][nt][2], acc[mt][nt][3]));
            }
        }
    }
}

// ---------------- K4: fused softmax + AV gather with smem-staged v ----------------
// grid (49, 128), 256 threads. v tile: 32 ch x 4 rows x 56 = 14 KB smem.
__global__ void __launch_bounds__(256) attn_av_kernel(
    const float* __restrict__ pos_emb, const float* __restrict__ Wlin) {
    __shared__ float sm_at[KWIN][64];
    __shared__ __align__(4) __half sv[32][4 * 56];     // [ch][r*56 + x]
    const int bh = blockIdx.y;
    const int b = bh >> 3, h = bh & 7;
    const int l0 = blockIdx.x * 64;
    const int tid = threadIdx.x;
    const int y0 = l0 / HDIM;

    // ---- stage v tile (rows y0-1 .. y0+2, zero-filled outside image) ----
    {
        const __half* vbase = g_v + (size_t)(b * DMODEL + h * NPH) * LTOT;
#pragma unroll
        for (int t = 0; t < 14; t++) {
            int idx = tid + t * 256;            // 0..3583 (32ch * 4r * 28 half2)
            int ch = idx / 112;
            int rem = idx - ch * 112;
            int r = rem / 28;
            int p2 = rem - r * 28;
            int gy = y0 - 1 + r;
            __half2 val = __float22half2_rn(make_float2(0.f, 0.f));
            if (gy >= 0 && gy < HDIM)
                val = *reinterpret_cast<const __half2*>(
                    vbase + (size_t)ch * LTOT + gy * HDIM + p2 * 2);
            *reinterpret_cast<__half2*>(&sv[ch][r * 56 + p2 * 2]) = val;
        }
    }

    // ---- softmax for 64 positions ----
    if (tid < 64) {
        float scale = Wlin[0] + Wlin[1] + Wlin[2] + Wlin[3];
        int l = l0 + tid;
        int y = l / HDIM, xx = l % HDIM;
        const float* sp = g_s + (size_t)bh * LTOT;
        float logit[KWIN];
#pragma unroll
        for (int kh = 0; kh < 3; kh++)
#pragma unroll
            for (int kw = 0; kw < 3; kw++) {
                int yy = y + kh - 1, xz = xx + kw - 1;
                float svl = (yy >= 0 && yy < HDIM && xz >= 0 && xz < HDIM)
                                ? sp[yy * HDIM + xz] : 0.f;
                logit[kh * 3 + kw] = svl + pos_emb[kh + kw];
            }
        float m = logit[0];
#pragma unroll
        for (int k = 1; k < KWIN; k++) m = fmaxf(m, logit[k]);
        float e[KWIN], sum = 0.f;
#pragma unroll
        for (int k = 0; k < KWIN; k++) { e[k] = __expf(logit[k] - m); sum += e[k]; }
        float inv = scale / sum;
#pragma unroll
        for (int k = 0; k < KWIN; k++) sm_at[k][tid] = e[k] * inv;
    }
    __syncthreads();

    // ---- gather from smem: thread = 2 l x 4 channels ----
    const int lp = tid & 31;
    const int dg = tid >> 5;
    float att[2][KWIN];
    int off[2][KWIN];
#pragma unroll
    for (int e = 0; e < 2; e++) {
        int ll = lp * 2 + e;
        int l = l0 + ll;
        int y = l / HDIM, xx = l % HDIM;
#pragma unroll
        for (int kh = 0; kh < 3; kh++)
#pragma unroll
            for (int kw = 0; kw < 3; kw++) {
                int k = kh * 3 + kw;
                int yy = y + kh - 1, xz = xx + kw - 1;
                bool ok = (yy >= 0 && yy < HDIM && xz >= 0 && xz < HDIM);
                att[e][k] = ok ? sm_at[k][ll] : 0.f;
                off[e][k] = ok ? (yy - (y0 - 1)) * 56 + xz : 0;
            }
    }
    const size_t obase = (size_t)(b * DMODEL + h * NPH + dg * 4) * LTOT;
#pragma unroll
    for (int dd = 0; dd < 4; dd++) {
        const __half* vp = &sv[dg * 4 + dd][0];
        float o[2];
#pragma unroll
        for (int e = 0; e < 2; e++) {
            float a = 0.f;
#pragma unroll
            for (int k = 0; k < KWIN; k++)
                a += att[e][k] * __half2float(vp[off[e][k]]);
            o[e] = a;
        }
        size_t oidx = obase + (size_t)dd * LTOT + l0 + lp * 2;
        *reinterpret_cast<__half2*>(g_ohi + oidx) =
            __float22half2_rn(make_float2(o[0], o[1]));
    }
}

// ---------------- host launcher ----------------
extern "C" void kernel_launch(void* const* d_in, const int* in_sizes, int n_in,
                              void* d_out, int out_size) {
    const float* x       = (const float*)d_in[0];
    const float* q       = (const float*)d_in[1];
    const float* Wk      = (const float*)d_in[2];
    const float* Wv      = (const float*)d_in[3];
    const float* pos_emb = (const float*)d_in[4];
    const float* Wlin    = (const float*)d_in[5];
    const float* Wproj   = (const float*)d_in[6];
    float* out = (float*)d_out;

    void *pv, *pxhi, *pohi, *pwvhi, *pwphi;
    cudaGetSymbolAddress(&pv, g_v);
    cudaGetSymbolAddress(&pxhi, g_xhi);
    cudaGetSymbolAddress(&pohi, g_ohi);
    cudaGetSymbolAddress(&pwvhi, g_wvhi);
    cudaGetSymbolAddress(&pwphi, g_wphi);

    static bool attr_set = false;
    if (!attr_set) {
        cudaFuncSetAttribute(hgemm<1, __half>,
                             cudaFuncAttributeMaxDynamicSharedMemorySize, 2 * 24576);
        cudaFuncSetAttribute(hgemm<1, float>,
                             cudaFuncAttributeMaxDynamicSharedMemorySize, 2 * 24576);
        attr_set = true;
    }

    const int WN4 = DMODEL * CIN / 4;

    wq_kernel<<<BATCH * HEADS, 256>>>(q, Wk);
    split_kernel<<<(WN4 + 255) / 256, 256>>>(Wv, (__half*)pwvhi, nullptr, WN4);
    split_kernel<<<(WN4 + 255) / 256, 256>>>(Wproj, (__half*)pwphi, nullptr, WN4);
    s_split_kernel<<<dim3(LTOT / 64, BATCH), 256>>>(x);

    hgemm<1, __half><<<dim3(LTOT / 64, DMODEL / 128, BATCH), 256, 2 * 24576>>>(
        (const __half*)pwvhi, nullptr, (const __half*)pxhi, (__half*)pv);

    attn_av_kernel<<<dim3(LTOT / 64, BATCH * HEADS), 256>>>(pos_emb, Wlin);

    hgemm<1, float><<<dim3(LTOT / 64, DMODEL / 128, BATCH), 256, 2 * 24576>>>(
        (const __half*)pwphi, nullptr, (const __half*)pohi, out);
}